// round 2
// baseline (speedup 1.0000x reference)
#include <cuda_runtime.h>
#include <cuda_bf16.h>

// Attention_64639257805512:
//   query [N_Q, D], keys [M, D], values [M, DV], tree_idx [M]
//   out = concat(att [N_Q, DV], alpha_sum [M])  (float32)
#define N_Q    4096
#define M_KEYS 32768
#define DDIM   512
#define DVDIM  512
#define CAP    8      // M / N_Q keys per group

// Scratch (device globals; zero-initialized at module load).
// g_cnt is re-zeroed by attn_fused_kernel at the end of every call, so no
// separate zeroing kernel is needed across graph replays.
__device__ int g_cnt[N_Q];
__device__ int g_list[N_Q * CAP];

__global__ void build_lists_kernel(const int* __restrict__ tree_idx) {
    int t = blockIdx.x * blockDim.x + threadIdx.x;   // one int4 per thread
    int4 v = ((const int4*)tree_idx)[t];
    int m0 = t * 4;
    int s;
    s = atomicAdd(&g_cnt[v.x], 1); if (s < CAP) g_list[v.x * CAP + s] = m0;
    s = atomicAdd(&g_cnt[v.y], 1); if (s < CAP) g_list[v.y * CAP + s] = m0 + 1;
    s = atomicAdd(&g_cnt[v.z], 1); if (s < CAP) g_list[v.z * CAP + s] = m0 + 2;
    s = atomicAdd(&g_cnt[v.w], 1); if (s < CAP) g_list[v.w * CAP + s] = m0 + 3;
}

// One block (256 threads, 8 warps) per query group.
__global__ __launch_bounds__(256) void attn_fused_kernel(
    const float* __restrict__ query,
    const float* __restrict__ keys,
    const float* __restrict__ values,
    float* __restrict__ att,        // [N_Q, DV]
    float* __restrict__ alpha_sum)  // [M]
{
    __shared__ float q_sh[DDIM];
    __shared__ float red_sh[8];
    __shared__ float s_sh[CAP];
    __shared__ float alpha_sh[CAP];
    __shared__ int   tmp_sh[CAP];
    __shared__ int   idx_sh[CAP];

    const int g    = blockIdx.x;
    const int tid  = threadIdx.x;
    const int wid  = tid >> 5;
    const int lane = tid & 31;

    int c = g_cnt[g];                 // all threads: broadcast load
    const int cnt = (c > CAP) ? CAP : c;
    if (tid < cnt) tmp_sh[tid] = g_list[g * CAP + tid];

    // Query row load (512 floats = 256 * float2) + sum-of-squares reduce.
    float2 qv = ((const float2*)(query + (size_t)g * DDIM))[tid];
    ((float2*)q_sh)[tid] = qv;
    float sq = qv.x * qv.x + qv.y * qv.y;
    #pragma unroll
    for (int o = 16; o > 0; o >>= 1) sq += __shfl_xor_sync(0xffffffffu, sq, o);
    if (lane == 0) red_sh[wid] = sq;
    __syncthreads();

    // Parallel rank sort of the (distinct) key indices -> deterministic order
    // regardless of atomic build order.
    if (tid < cnt) {
        int v = tmp_sh[tid];
        int r = 0;
        for (int j = 0; j < cnt; j++) r += (tmp_sh[j] < v);
        idx_sh[r] = v;
    }
    __syncthreads();

    // Prefetch ALL value rows into registers NOW, so the loads are in flight
    // during the key-dot phase and softmax (removes serial dependency).
    float2 vreg[CAP];
    if (cnt == CAP) {
        #pragma unroll
        for (int j = 0; j < CAP; j++)
            vreg[j] = ((const float2*)(values + (size_t)idx_sh[j] * DVDIM))[tid];
    } else {
        #pragma unroll
        for (int j = 0; j < CAP; j++)
            vreg[j] = (j < cnt)
                ? ((const float2*)(values + (size_t)idx_sh[j] * DVDIM))[tid]
                : make_float2(0.f, 0.f);
    }

    // One warp per owned key: dot(q,k) and ||k||^2 via float4 loads.
    if (wid < cnt) {
        const int m = idx_sh[wid];
        const float4* krow = (const float4*)(keys + (size_t)m * DDIM);
        const float4* qrow = (const float4*)q_sh;
        float dot = 0.f, ksq = 0.f;
        #pragma unroll
        for (int i = 0; i < 4; i++) {
            float4 k = krow[lane + i * 32];
            float4 q = qrow[lane + i * 32];
            dot += k.x * q.x + k.y * q.y + k.z * q.z + k.w * q.w;
            ksq += k.x * k.x + k.y * k.y + k.z * k.z + k.w * k.w;
        }
        #pragma unroll
        for (int o = 16; o > 0; o >>= 1) {
            dot += __shfl_xor_sync(0xffffffffu, dot, o);
            ksq += __shfl_xor_sync(0xffffffffu, ksq, o);
        }
        if (lane == 0)
            s_sh[wid] = dot * rsqrtf(fmaxf(ksq, 1e-24f));  // q-norm folded in below
    }
    __syncthreads();

    // Softmax over <=8 scores (single thread; trivial). Fold in 1/||q|| here.
    if (tid == 0) {
        float t = 0.f;
        #pragma unroll
        for (int i = 0; i < 8; i++) t += red_sh[i];
        float qinv = rsqrtf(fmaxf(t, 1e-24f));   // 1/max(||q||, 1e-12)
        float mx = -1e30f;
        for (int j = 0; j < cnt; j++) { s_sh[j] *= qinv; mx = fmaxf(mx, s_sh[j]); }
        float sum = 0.f;
        for (int j = 0; j < cnt; j++) {
            float e = expf(s_sh[j] - mx);
            alpha_sh[j] = e;
            sum += e;
        }
        float inv = 1.f / sum;
        for (int j = 0; j < cnt; j++) alpha_sh[j] *= inv;
        g_cnt[g] = 0;   // reset counter for the next kernel_launch call
    }
    __syncthreads();

    // alpha.sum(axis=0)[m] == alpha of key m within its own group.
    if (tid < cnt) alpha_sum[idx_sh[tid]] = alpha_sh[tid];

    // att[g] = sum_j alpha_j * v_j  — pure register FMAs now.
    float2 acc = make_float2(0.f, 0.f);
    #pragma unroll
    for (int j = 0; j < CAP; j++) {
        if (j < cnt) {
            const float a = alpha_sh[j];
            acc.x += a * vreg[j].x;
            acc.y += a * vreg[j].y;
        }
    }
    ((float2*)(att + (size_t)g * DVDIM))[tid] = acc;
}

extern "C" void kernel_launch(void* const* d_in, const int* in_sizes, int n_in,
                              void* d_out, int out_size) {
    const float* query  = (const float*)d_in[0];
    const float* keys   = (const float*)d_in[1];
    const float* values = (const float*)d_in[2];
    const int*   tree   = (const int*)d_in[3];

    float* att  = (float*)d_out;                       // [N_Q, DV]
    float* asum = (float*)d_out + (size_t)N_Q * DVDIM; // [M]

    build_lists_kernel<<<M_KEYS / 4 / 256, 256>>>(tree);
    attn_fused_kernel<<<N_Q, 256>>>(query, keys, values, att, asum);
}